// round 2
// baseline (speedup 1.0000x reference)
#include <cuda_runtime.h>

// Shapes are fixed by the problem: B=2, H=8, N=256, D=64.
#define NQ 256
#define DD 64

// SMEM layout (floats)
#define SQK_STRIDE 257   // [64][257]  Qh transposed (d-major), odd stride -> conflict-free
#define SP_STRIDE  68    // [256][68]  P panel (exp'd logits), 16B-aligned rows
#define S64        68    // [64][68]   k2 panel / v1 chunk

static constexpr int SQK1_OFF = 0;
static constexpr int SP_OFF   = SQK1_OFF + 64 * SQK_STRIDE;   // 16448
static constexpr int SK2_OFF  = SP_OFF   + 256 * SP_STRIDE;   // +17408
static constexpr int SV_OFF   = SK2_OFF  + 64 * S64;          // +4352
static constexpr int SRED_OFF = SV_OFF   + 64 * S64;          // +4352
static constexpr int SO_OFF   = SRED_OFF + 16 * S64;          // +1088
static constexpr int SL_OFF   = SO_OFF + 64;
static constexpr int SLP_OFF  = SL_OFF + 1;
static constexpr int SMEM_FLOATS = SLP_OFF + 8 + 3;
static constexpr int SMEM_BYTES  = SMEM_FLOATS * 4;           // ~174.9 KB

__global__ __launch_bounds__(256, 1)
void trisimp_kernel(const float* __restrict__ q,
                    const float* __restrict__ k1,
                    const float* __restrict__ v1,
                    const float* __restrict__ k2,
                    const float* __restrict__ v2,
                    float* __restrict__ out)
{
    extern __shared__ float sm[];
    float* sQK1 = sm + SQK1_OFF;   // [d][j]  Qh = q_d * k1[j][d]
    float* sP   = sm + SP_OFF;     // [j][k]  exp(logits) panel
    float* sK2  = sm + SK2_OFF;    // [d][k]  k2 panel (transposed)
    float* sV   = sm + SV_OFF;     // [jl][d] v1 chunk
    float* sRed = sm + SRED_OFF;   // [16][d] partial k-reductions
    float* sO   = sm + SO_OFF;     // [64]    output accumulator
    float* sL   = sm + SL_OFF;     // [1]     sum of exps
    float* sLp  = sm + SLP_OFF;    // [8]     per-warp partial sums

    const int tid = threadIdx.x;
    const int bhq = blockIdx.x;          // 0..4095
    const int qi  = bhq & 255;
    const int bh  = bhq >> 8;
    const size_t base = (size_t)bh * NQ * DD;
    const float* Q  = q  + base + (size_t)qi * DD;
    const float* K1 = k1 + base;
    const float* V1 = v1 + base;
    const float* K2 = k2 + base;
    const float* V2 = v2 + base;

    if (tid < 64) sO[tid] = 0.f;
    if (tid == 0) sL[0] = 0.f;

    // Build Qh transposed: sQK1[d][j] = Q[d] * K1[j][d].
    // i = tid + n*256 => d = i&63 is constant per thread; K1 reads coalesced;
    // SMEM writes stride-257 => bank (d + j) % 32, conflict-free.
    {
        const float qd = Q[tid & 63];
        for (int i = tid; i < NQ * DD; i += 256)
            sQK1[(i & 63) * SQK_STRIDE + (i >> 6)] = qd * K1[i];
    }
    __syncthreads();

    const int tj = tid >> 3;   // 0..31 : 8 j-rows each (GEMM1)
    const int tk = tid & 7;    // 0..7  : 8 k-cols each (GEMM1)
    const int kt = tid >> 4;   // 0..15 : 4 k each (GEMM2)
    const int dt = tid & 15;   // 0..15 : 4 d each (GEMM2)
    const int wid = tid >> 5;

    for (int panel = 0; panel < 4; ++panel) {
        const int k0p = panel * 64;

        // Stage sK2[d][k] = K2[k0p+k][d] (coalesced global reads).
        for (int i = tid; i < 64 * 64; i += 256) {
            const int kk = i >> 6, d = i & 63;
            sK2[d * S64 + kk] = K2[(size_t)(k0p + kk) * DD + d];
        }
        __syncthreads();

        // ---- GEMM1: S[j,k] = sum_d Qh[j,d] * k2[k,d]  (8x8 per thread) ----
        float acc[8][8];
        #pragma unroll
        for (int a = 0; a < 8; ++a)
            #pragma unroll
            for (int b = 0; b < 8; ++b) acc[a][b] = 0.f;

        #pragma unroll 8
        for (int d = 0; d < 64; ++d) {
            float av[8], bv[8];
            const float* arow = &sQK1[d * SQK_STRIDE + tj * 8];
            #pragma unroll
            for (int x = 0; x < 8; ++x) av[x] = arow[x];   // broadcast-friendly loads
            const float4 b0 = *(const float4*)&sK2[d * S64 + tk * 8];
            const float4 b1 = *(const float4*)&sK2[d * S64 + tk * 8 + 4];
            bv[0] = b0.x; bv[1] = b0.y; bv[2] = b0.z; bv[3] = b0.w;
            bv[4] = b1.x; bv[5] = b1.y; bv[6] = b1.z; bv[7] = b1.w;
            #pragma unroll
            for (int jj = 0; jj < 8; ++jj)
                #pragma unroll
                for (int kk = 0; kk < 8; ++kk)
                    acc[jj][kk] = fmaf(av[jj], bv[kk], acc[jj][kk]);
        }

        // ---- exp (no max-subtraction needed: |logit| < ~50 whp) + sum ----
        float lsum = 0.f;
        #pragma unroll
        for (int jj = 0; jj < 8; ++jj) {
            #pragma unroll
            for (int kk = 0; kk < 8; ++kk) {
                const float p = __expf(acc[jj][kk]);
                lsum += p;
                sP[(tj * 8 + jj) * SP_STRIDE + tk * 8 + kk] = p;
            }
        }
        #pragma unroll
        for (int off = 16; off; off >>= 1)
            lsum += __shfl_xor_sync(0xffffffffu, lsum, off);
        if ((tid & 31) == 0) sLp[wid] = lsum;
        __syncthreads();
        if (tid == 0) {   // deterministic accumulation order
            float s = 0.f;
            #pragma unroll
            for (int w = 0; w < 8; ++w) s += sLp[w];
            sL[0] += s;
        }

        // ---- GEMM2: T[k,d] = sum_j P[j,k] * v1[j,d]  (4x4 per thread) ----
        float T[4][4];
        #pragma unroll
        for (int a = 0; a < 4; ++a)
            #pragma unroll
            for (int b = 0; b < 4; ++b) T[a][b] = 0.f;

        for (int jc = 0; jc < 4; ++jc) {
            __syncthreads();   // previous sV readers done (and sP/sLp users, on jc==0)
            for (int t = tid; t < 1024; t += 256) {
                const int jl = t >> 4, d4 = t & 15;
                *(float4*)&sV[jl * S64 + d4 * 4] =
                    *(const float4*)&V1[(size_t)(jc * 64 + jl) * DD + d4 * 4];
            }
            __syncthreads();
            #pragma unroll 8
            for (int jl = 0; jl < 64; ++jl) {
                const float4 pv = *(const float4*)&sP[(jc * 64 + jl) * SP_STRIDE + kt * 4];
                const float4 vv = *(const float4*)&sV[jl * S64 + dt * 4];
                const float pk[4] = {pv.x, pv.y, pv.z, pv.w};
                const float vd[4] = {vv.x, vv.y, vv.z, vv.w};
                #pragma unroll
                for (int kk = 0; kk < 4; ++kk)
                    #pragma unroll
                    for (int dd = 0; dd < 4; ++dd)
                        T[kk][dd] = fmaf(pk[kk], vd[dd], T[kk][dd]);
            }
        }

        // ---- epilogue: O[d] += sum_k T[k,d] * v2[k,d] ----
        float r[4] = {0.f, 0.f, 0.f, 0.f};
        #pragma unroll
        for (int kk = 0; kk < 4; ++kk) {
            const int kg = k0p + kt * 4 + kk;
            const float4 v2v = *(const float4*)&V2[(size_t)kg * DD + dt * 4];
            r[0] = fmaf(T[kk][0], v2v.x, r[0]);
            r[1] = fmaf(T[kk][1], v2v.y, r[1]);
            r[2] = fmaf(T[kk][2], v2v.z, r[2]);
            r[3] = fmaf(T[kk][3], v2v.w, r[3]);
        }
        __syncthreads();   // all T finished; sRed region free to write
        *(float4*)&sRed[kt * S64 + dt * 4] = make_float4(r[0], r[1], r[2], r[3]);
        __syncthreads();
        if (tid < 64) {
            float s = 0.f;
            #pragma unroll
            for (int t2 = 0; t2 < 16; ++t2) s += sRed[t2 * S64 + tid];
            sO[tid] += s;
        }
        __syncthreads();   // before next panel overwrites sK2/sP/sRed
    }

    if (tid < 64)
        out[base + (size_t)qi * DD + tid] = sO[tid] / sL[0];
}

extern "C" void kernel_launch(void* const* d_in, const int* in_sizes, int n_in,
                              void* d_out, int out_size)
{
    const float* q  = (const float*)d_in[0];
    const float* k1 = (const float*)d_in[1];
    const float* v1 = (const float*)d_in[2];
    const float* k2 = (const float*)d_in[3];
    const float* v2 = (const float*)d_in[4];
    // d_in[5] = chunk_size (unused; the math is chunking-invariant)
    float* out = (float*)d_out;

    (void)cudaFuncSetAttribute(trisimp_kernel,
                               cudaFuncAttributeMaxDynamicSharedMemorySize, SMEM_BYTES);
    trisimp_kernel<<<2 * 8 * NQ, 256, SMEM_BYTES>>>(q, k1, v1, k2, v2, out);
}

// round 4
// speedup vs baseline: 3.4436x; 3.4436x over previous
#include <cuda_runtime.h>
#include <cuda_bf16.h>
#include <cstdint>

// Fixed shapes: B=2, H=8, N=256, D=64.  One CTA per (b,h,q) query.
#define NQ 256
#define DD 64
#define NPANEL 4

// SMEM byte offsets. Rows padded to 144B (16B-aligned, bank-rotating) so every
// ldmatrix phase (8 rows x 16B) hits 8 distinct bank groups.
#define RS 144
static constexpr uint32_t OFF_K2H = 0;                       // [256 k][64 d] bf16 hi
static constexpr uint32_t OFF_K2L = 36864;
static constexpr uint32_t OFF_QHH = 73728;                   // [256 j][64 d] bf16 hi (q*k1*log2e)
static constexpr uint32_t OFF_QHL = 110592;
static constexpr uint32_t OFF_V1H = 147456;                  // [64 j][64 d] bf16 hi (panel)
static constexpr uint32_t OFF_V1L = 156672;
static constexpr uint32_t OFF_SRED = 165888;                 // [8 warps][64 d] fp32
static constexpr uint32_t OFF_SLP  = 167936;                 // [8] fp32 lsum partials
static constexpr uint32_t SMEM_BYTES = 168064;

// ---------------- PTX helpers ----------------------------------------------
__device__ __forceinline__ uint32_t smem_u32(const void* p) {
    uint32_t a;
    asm("{ .reg .u64 t; cvta.to.shared.u64 t, %1; cvt.u32.u64 %0, t; }" : "=r"(a) : "l"(p));
    return a;
}
__device__ __forceinline__ float ex2f(float x) {
    float y; asm("ex2.approx.ftz.f32 %0, %1;" : "=f"(y) : "f"(x)); return y;
}
__device__ __forceinline__ void ldsm_x4(uint32_t* r, uint32_t addr) {
    asm volatile("ldmatrix.sync.aligned.m8n8.x4.shared.b16 {%0,%1,%2,%3}, [%4];"
                 : "=r"(r[0]), "=r"(r[1]), "=r"(r[2]), "=r"(r[3]) : "r"(addr));
}
__device__ __forceinline__ void ldsm_x4_t(uint32_t* r, uint32_t addr) {
    asm volatile("ldmatrix.sync.aligned.m8n8.x4.trans.shared.b16 {%0,%1,%2,%3}, [%4];"
                 : "=r"(r[0]), "=r"(r[1]), "=r"(r[2]), "=r"(r[3]) : "r"(addr));
}
__device__ __forceinline__ void mma16816(float* c, const uint32_t* a, uint32_t b0, uint32_t b1) {
    asm volatile("mma.sync.aligned.m16n8k16.row.col.f32.bf16.bf16.f32 "
                 "{%0,%1,%2,%3}, {%4,%5,%6,%7}, {%8,%9}, {%0,%1,%2,%3};"
                 : "+f"(c[0]), "+f"(c[1]), "+f"(c[2]), "+f"(c[3])
                 : "r"(a[0]), "r"(a[1]), "r"(a[2]), "r"(a[3]), "r"(b0), "r"(b1));
}
// split (x,y) into bf16 hi pair and bf16 residual-lo pair (packed b16x2, x in low half)
__device__ __forceinline__ void split2(float x, float y, uint32_t& h, uint32_t& l) {
    __nv_bfloat162 h2 = __floats2bfloat162_rn(x, y);
    __nv_bfloat162 l2 = __floats2bfloat162_rn(x - __low2float(h2), y - __high2float(h2));
    h = *(uint32_t*)&h2; l = *(uint32_t*)&l2;
}

// ---------------- Kernel ----------------------------------------------------
__global__ __launch_bounds__(256, 1)
void trisimp_mma_kernel(const float* __restrict__ q,  const float* __restrict__ k1,
                        const float* __restrict__ v1, const float* __restrict__ k2,
                        const float* __restrict__ v2, float* __restrict__ out)
{
    extern __shared__ char smem[];
    const uint32_t sb = smem_u32(smem);
    const int tid = threadIdx.x, w = tid >> 5, lid = tid & 31;
    const int g = lid >> 2, t = lid & 3;

    const int bhq = blockIdx.x, qi = bhq & 255, bh = bhq >> 8;
    const size_t base = (size_t)bh * NQ * DD;
    const float* Qrow = q  + base + (size_t)qi * DD;
    const float* K1g  = k1 + base;
    const float* V1g  = v1 + base;
    const float* K2g  = k2 + base;
    const float* V2g  = v2 + base;

    // ---- stage K2 hi/lo and Qh hi/lo: rows [row][64 d], 144B row stride ----
    {
        const float2* K2g2 = (const float2*)K2g;
        const float2* K1g2 = (const float2*)K1g;
        const int dp = tid & 31;                     // constant per thread (256 % 32 == 0)
        const float2 qp = ((const float2*)Qrow)[dp];
        const float qx = qp.x * 1.4426950408889634f;
        const float qy = qp.y * 1.4426950408889634f;
        for (int e2 = tid; e2 < NQ * 32; e2 += 256) {
            const int r = e2 >> 5;
            const uint32_t off = (uint32_t)r * RS + (uint32_t)dp * 4;
            {
                const float2 x = K2g2[e2];
                uint32_t h, l; split2(x.x, x.y, h, l);
                *(uint32_t*)(smem + OFF_K2H + off) = h;
                *(uint32_t*)(smem + OFF_K2L + off) = l;
            }
            {
                const float2 x = K1g2[e2];
                uint32_t h, l; split2(qx * x.x, qy * x.y, h, l);
                *(uint32_t*)(smem + OFF_QHH + off) = h;
                *(uint32_t*)(smem + OFF_QHL + off) = l;
            }
        }
    }

    // ldmatrix address templates
    const uint32_t lm_a  = (uint32_t)(lid & 15) * RS + (uint32_t)(lid >> 4) * 16;          // A / trans-B
    const uint32_t lm_b  = (uint32_t)((lid >> 4) * 8 + (lid & 7)) * RS + (uint32_t)((lid >> 3) & 1) * 16; // non-trans B

    float o[2][8][4];                                 // D2 accum: [mt][d-tile][frag]
    #pragma unroll
    for (int mt = 0; mt < 2; ++mt)
        #pragma unroll
        for (int nt = 0; nt < 8; ++nt)
            #pragma unroll
            for (int r = 0; r < 4; ++r) o[mt][nt][r] = 0.f;
    float lsum = 0.f;

    #pragma unroll 1
    for (int p = 0; p < NPANEL; ++p) {
        __syncthreads();                              // V1 buffer free (and staging done, p==0)
        // ---- stage V1 panel hi/lo [64 j][64 d] ----
        {
            const float2* V1p2 = (const float2*)(V1g + (size_t)p * 64 * DD);
            const int dp = tid & 31;
            for (int e2 = tid; e2 < 64 * 32; e2 += 256) {
                const int r = e2 >> 5;
                const float2 x = V1p2[e2];
                uint32_t h, l; split2(x.x, x.y, h, l);
                const uint32_t off = (uint32_t)r * RS + (uint32_t)dp * 4;
                *(uint32_t*)(smem + OFF_V1H + off) = h;
                *(uint32_t*)(smem + OFF_V1L + off) = l;
            }
        }
        __syncthreads();                              // V1 ready

        // ---- GEMM1: S[k, j] = sum_d K2[k,d] * Qh[j,d]  (hi/lo 3-product) ----
        float s[2][8][4];
        #pragma unroll
        for (int mt = 0; mt < 2; ++mt)
            #pragma unroll
            for (int nt = 0; nt < 8; ++nt)
                #pragma unroll
                for (int r = 0; r < 4; ++r) s[mt][nt][r] = 0.f;

        #pragma unroll
        for (int kc = 0; kc < 4; ++kc) {              // d-chunks of 16
            uint32_t aH[2][4], aL[2][4];
            #pragma unroll
            for (int mt = 0; mt < 2; ++mt) {
                const uint32_t rowb = (uint32_t)(32 * w + 16 * mt) * RS + (uint32_t)kc * 32;
                ldsm_x4(aH[mt], sb + OFF_K2H + rowb + lm_a);
                ldsm_x4(aL[mt], sb + OFF_K2L + rowb + lm_a);
            }
            #pragma unroll
            for (int cp = 0; cp < 4; ++cp) {          // j-tile pairs
                uint32_t bH[4], bL[4];
                const uint32_t rowb = (uint32_t)(64 * p + 16 * cp) * RS + (uint32_t)kc * 32;
                ldsm_x4(bH, sb + OFF_QHH + rowb + lm_b);   // {b0_n0,b1_n0,b0_n1,b1_n1}
                ldsm_x4(bL, sb + OFF_QHL + rowb + lm_b);
                #pragma unroll
                for (int h = 0; h < 2; ++h) {
                    const int nt = 2 * cp + h;
                    #pragma unroll
                    for (int mt = 0; mt < 2; ++mt) {
                        mma16816(s[mt][nt], aH[mt], bH[2*h], bH[2*h+1]);
                        mma16816(s[mt][nt], aH[mt], bL[2*h], bL[2*h+1]);
                        mma16816(s[mt][nt], aL[mt], bH[2*h], bH[2*h+1]);
                    }
                }
            }
        }

        // ---- per j16-chunk: exp2, pack P hi/lo as A-frags, GEMM2 ----
        #pragma unroll
        for (int c = 0; c < 4; ++c) {
            uint32_t paH[2][4], paL[2][4];
            #pragma unroll
            for (int mt = 0; mt < 2; ++mt) {
                #pragma unroll
                for (int h = 0; h < 2; ++h) {
                    float* cc = s[mt][2 * c + h];
                    const float p0 = ex2f(cc[0]), p1 = ex2f(cc[1]);
                    const float p2 = ex2f(cc[2]), p3 = ex2f(cc[3]);
                    lsum += (p0 + p1) + (p2 + p3);
                    split2(p0, p1, paH[mt][2*h],   paL[mt][2*h]);     // rows g   (a0/a2)
                    split2(p2, p3, paH[mt][2*h+1], paL[mt][2*h+1]);   // rows g+8 (a1/a3)
                }
            }
            #pragma unroll
            for (int ntp = 0; ntp < 4; ++ntp) {       // d-tile pairs
                uint32_t vH[4], vL[4];
                const uint32_t rowb = (uint32_t)(16 * c) * RS + (uint32_t)ntp * 32;
                ldsm_x4_t(vH, sb + OFF_V1H + rowb + lm_a);   // {b0_d0,b1_d0,b0_d1,b1_d1}
                ldsm_x4_t(vL, sb + OFF_V1L + rowb + lm_a);
                #pragma unroll
                for (int h = 0; h < 2; ++h) {
                    const int nt = 2 * ntp + h;
                    #pragma unroll
                    for (int mt = 0; mt < 2; ++mt) {
                        mma16816(o[mt][nt], paH[mt], vH[2*h], vH[2*h+1]);
                        mma16816(o[mt][nt], paH[mt], vL[2*h], vL[2*h+1]);
                        mma16816(o[mt][nt], paL[mt], vH[2*h], vH[2*h+1]);
                    }
                }
            }
        }
    }

    // ---- epilogue: out[d] = sum_k D2[k,d] * v2[k,d] / sum(exp) ----
    float* sRed = (float*)(smem + OFF_SRED);
    float* sLp  = (float*)(smem + OFF_SLP);
    {
        const int k0 = 32 * w + g;
        #pragma unroll
        for (int nt = 0; nt < 8; ++nt) {
            const int d0 = 8 * nt + 2 * t;
            const float2 vA = *(const float2*)(V2g + (size_t)(k0)      * DD + d0);
            const float2 vB = *(const float2*)(V2g + (size_t)(k0 + 8)  * DD + d0);
            const float2 vC = *(const float2*)(V2g + (size_t)(k0 + 16) * DD + d0);
            const float2 vD = *(const float2*)(V2g + (size_t)(k0 + 24) * DD + d0);
            float r0 = o[0][nt][0]*vA.x + o[0][nt][2]*vB.x + o[1][nt][0]*vC.x + o[1][nt][2]*vD.x;
            float r1 = o[0][nt][1]*vA.y + o[0][nt][3]*vB.y + o[1][nt][1]*vC.y + o[1][nt][3]*vD.y;
            #pragma unroll
            for (int m = 4; m <= 16; m <<= 1) {       // reduce over g (rows)
                r0 += __shfl_xor_sync(0xffffffffu, r0, m);
                r1 += __shfl_xor_sync(0xffffffffu, r1, m);
            }
            if (g == 0) *(float2*)(sRed + w * 64 + d0) = make_float2(r0, r1);
        }
        #pragma unroll
        for (int m = 16; m; m >>= 1)
            lsum += __shfl_xor_sync(0xffffffffu, lsum, m);
        if (lid == 0) sLp[w] = lsum;
    }
    __syncthreads();

    if (tid < 64) {
        float ssum = 0.f;
        #pragma unroll
        for (int ww = 0; ww < 8; ++ww) ssum += sRed[ww * 64 + tid];
        float l = 0.f;
        #pragma unroll
        for (int ww = 0; ww < 8; ++ww) l += sLp[ww];
        out[base + (size_t)qi * DD + tid] = ssum / l;
    }
}

extern "C" void kernel_launch(void* const* d_in, const int* in_sizes, int n_in,
                              void* d_out, int out_size)
{
    const float* q  = (const float*)d_in[0];
    const float* k1 = (const float*)d_in[1];
    const float* v1 = (const float*)d_in[2];
    const float* k2 = (const float*)d_in[3];
    const float* v2 = (const float*)d_in[4];
    float* out = (float*)d_out;

    (void)cudaFuncSetAttribute(trisimp_mma_kernel,
                               cudaFuncAttributeMaxDynamicSharedMemorySize, SMEM_BYTES);
    trisimp_mma_kernel<<<2 * 8 * NQ, 256, SMEM_BYTES>>>(q, k1, v1, k2, v2, out);
}